// round 1
// baseline (speedup 1.0000x reference)
#include <cuda_runtime.h>
#include <math_constants.h>

// Problem constants
#define B 4
#define N 2048
#define DIM 1024
#define HEADS 8
#define DQK 64
#define DV 128
#define MAX_POS 10
#define SCALE 0.125f   // 64^-0.5
#define BN_ROWS (B*N)  // 8192

// -------- scratch (device globals: allocation-free) --------
__device__ float g_qk[(size_t)BN_ROWS * DIM];  // q | k packed: [8192, 1024]
__device__ float g_v [(size_t)BN_ROWS * DIM];  // [8192, 1024]
__device__ float g_ao[(size_t)BN_ROWS * DIM];  // attention output [8192, 1024]

// ======================= SGEMM 128x128x8 =======================
// C[M,N] = A[M,K] @ Bm[K,N] (+ bias[N] if bias != nullptr). Row-major.
#define GBM 128
#define GBN 128
#define GBK 8

__global__ __launch_bounds__(256)
void sgemm_kernel(const float* __restrict__ A, const float* __restrict__ Bm,
                  const float* __restrict__ bias, float* __restrict__ C,
                  int M, int Nn, int K)
{
    __shared__ float As[GBK][GBM];
    __shared__ float Bs[GBK][GBN];

    const int tid = threadIdx.x;
    const int bx = blockIdx.x, by = blockIdx.y;
    const int tx = tid & 15, ty = tid >> 4;

    // global load indices
    const int aRow  = tid >> 1;          // 0..127
    const int aCol4 = (tid & 1) << 2;    // 0 or 4
    const int bRow  = tid >> 5;          // 0..7
    const int bCol4 = (tid & 31) << 2;   // 0..124

    const float* Ablk = A  + (size_t)(by * GBM) * K;
    const float* Bblk = Bm + (size_t)(bx * GBN);

    float acc[8][8];
    #pragma unroll
    for (int i = 0; i < 8; i++)
        #pragma unroll
        for (int j = 0; j < 8; j++) acc[i][j] = 0.f;

    for (int k0 = 0; k0 < K; k0 += GBK) {
        float4 a4 = *(const float4*)(Ablk + (size_t)aRow * K + k0 + aCol4);
        As[aCol4 + 0][aRow] = a4.x;
        As[aCol4 + 1][aRow] = a4.y;
        As[aCol4 + 2][aRow] = a4.z;
        As[aCol4 + 3][aRow] = a4.w;

        float4 b4 = *(const float4*)(Bblk + (size_t)(k0 + bRow) * Nn + bCol4);
        *(float4*)&Bs[bRow][bCol4] = b4;

        __syncthreads();

        #pragma unroll
        for (int k = 0; k < GBK; k++) {
            float aF[8], bF[8];
            float4 a0 = *(float4*)&As[k][ty * 8];
            float4 a1 = *(float4*)&As[k][ty * 8 + 4];
            aF[0]=a0.x; aF[1]=a0.y; aF[2]=a0.z; aF[3]=a0.w;
            aF[4]=a1.x; aF[5]=a1.y; aF[6]=a1.z; aF[7]=a1.w;
            float4 b0 = *(float4*)&Bs[k][tx * 8];
            float4 b1 = *(float4*)&Bs[k][tx * 8 + 4];
            bF[0]=b0.x; bF[1]=b0.y; bF[2]=b0.z; bF[3]=b0.w;
            bF[4]=b1.x; bF[5]=b1.y; bF[6]=b1.z; bF[7]=b1.w;
            #pragma unroll
            for (int i = 0; i < 8; i++)
                #pragma unroll
                for (int j = 0; j < 8; j++)
                    acc[i][j] += aF[i] * bF[j];
        }
        __syncthreads();
    }

    // epilogue
    #pragma unroll
    for (int i = 0; i < 8; i++) {
        int row = by * GBM + ty * 8 + i;
        float* crow = C + (size_t)row * Nn + bx * GBN + tx * 8;
        float4 c0, c1;
        if (bias != nullptr) {
            const float* brow = bias + bx * GBN + tx * 8;
            c0.x = acc[i][0] + brow[0]; c0.y = acc[i][1] + brow[1];
            c0.z = acc[i][2] + brow[2]; c0.w = acc[i][3] + brow[3];
            c1.x = acc[i][4] + brow[4]; c1.y = acc[i][5] + brow[5];
            c1.z = acc[i][6] + brow[6]; c1.w = acc[i][7] + brow[7];
        } else {
            c0.x = acc[i][0]; c0.y = acc[i][1]; c0.z = acc[i][2]; c0.w = acc[i][3];
            c1.x = acc[i][4]; c1.y = acc[i][5]; c1.z = acc[i][6]; c1.w = acc[i][7];
        }
        *(float4*)(crow)     = c0;
        *(float4*)(crow + 4) = c1;
    }
}

// ======================= Flash attention =======================
// Grid: (N/16, HEADS, B). 256 threads = 8 warps, each warp handles 2 query rows.
// Streams K/V in 128-key tiles through dynamic smem. Online softmax.
#define KT 128
#define ROWS 16
#define KPAD 65

// floats: Ks KT*65=8320 | Vs KT*128=16384 | Qs 16*64=1024 | Ps 16*128=2048 | Cv 32
#define SM_KS   0
#define SM_VS   (SM_KS + KT*KPAD)
#define SM_QS   (SM_VS + KT*DV)
#define SM_PS   (SM_QS + ROWS*DQK)
#define SM_CV   (SM_PS + ROWS*KT)
#define SM_FLOATS (SM_CV + 32)
#define ATTN_SMEM_BYTES (SM_FLOATS * 4)

__device__ __forceinline__ float warp_max(float v) {
    #pragma unroll
    for (int o = 16; o > 0; o >>= 1) v = fmaxf(v, __shfl_xor_sync(0xffffffffu, v, o));
    return v;
}
__device__ __forceinline__ float warp_sum(float v) {
    #pragma unroll
    for (int o = 16; o > 0; o >>= 1) v += __shfl_xor_sync(0xffffffffu, v, o);
    return v;
}

__global__ __launch_bounds__(256)
void attn_kernel(const float* __restrict__ qk, const float* __restrict__ vbuf,
                 const float* __restrict__ conv, float* __restrict__ out)
{
    extern __shared__ float sm[];
    float* Ks = sm + SM_KS;
    float* Vs = sm + SM_VS;
    float* Qs = sm + SM_QS;
    float* Ps = sm + SM_PS;
    float* Cv = sm + SM_CV;

    const int tid  = threadIdx.x;
    const int lane = tid & 31;
    const int w    = tid >> 5;
    const int h    = blockIdx.y;
    const int b    = blockIdx.z;
    const int i0   = blockIdx.x * ROWS;

    if (tid < 2 * MAX_POS + 1) Cv[tid] = conv[h * (2 * MAX_POS + 1) + tid];

    // load Q rows [i0, i0+16) for this head: 16 rows x 64 = 256 float4, one per thread
    {
        int rr = tid >> 4;           // 0..15
        int d4 = (tid & 15) << 2;    // 0..60
        const float* qrow = qk + ((size_t)(b * N + i0 + rr)) * DIM + h * DQK;
        *(float4*)&Qs[rr * DQK + d4] = *(const float4*)(qrow + d4);
    }
    __syncthreads();

    const int r0 = w * 2, r1 = w * 2 + 1;
    const int iq0 = i0 + r0, iq1 = i0 + r1;

    float m0 = -CUDART_INF_F, m1 = -CUDART_INF_F;
    float l0 = 0.f, l1 = 0.f;
    float acc0[4] = {0.f, 0.f, 0.f, 0.f};
    float acc1[4] = {0.f, 0.f, 0.f, 0.f};

    for (int j0 = 0; j0 < N; j0 += KT) {
        // --- cooperative load K tile (128x64) and V tile (128x128) ---
        #pragma unroll
        for (int t = tid; t < KT * 16; t += 256) {   // 2048 float4
            int row = t >> 4;
            int d4  = (t & 15) << 2;
            float4 kv = *(const float4*)(qk + ((size_t)(b * N + j0 + row)) * DIM
                                          + HEADS * DQK + h * DQK + d4);
            float* dst = &Ks[row * KPAD + d4];
            dst[0] = kv.x; dst[1] = kv.y; dst[2] = kv.z; dst[3] = kv.w;
        }
        #pragma unroll
        for (int t = tid; t < KT * 32; t += 256) {   // 4096 float4
            int row = t >> 5;
            int d4  = (t & 31) << 2;
            float4 vv = *(const float4*)(vbuf + ((size_t)(b * N + j0 + row)) * DIM
                                          + h * DV + d4);
            *(float4*)&Vs[row * DV + d4] = vv;
        }
        __syncthreads();

        // --- QK^T: each lane handles 4 keys (lane + 32u) for 2 rows ---
        float s0[4] = {0.f, 0.f, 0.f, 0.f};
        float s1[4] = {0.f, 0.f, 0.f, 0.f};
        const float* q0p = &Qs[r0 * DQK];
        const float* q1p = &Qs[r1 * DQK];
        #pragma unroll 4
        for (int d = 0; d < DQK; d++) {
            float q0 = q0p[d], q1 = q1p[d];
            #pragma unroll
            for (int u = 0; u < 4; u++) {
                float kv = Ks[(lane + 32 * u) * KPAD + d];
                s0[u] += q0 * kv;
                s1[u] += q1 * kv;
            }
        }
        // scale + relative-position bias
        #pragma unroll
        for (int u = 0; u < 4; u++) {
            int j = j0 + lane + 32 * u;
            int d0 = min(max(j - iq0, -MAX_POS), MAX_POS) + MAX_POS;
            int d1 = min(max(j - iq1, -MAX_POS), MAX_POS) + MAX_POS;
            s0[u] = s0[u] * SCALE + Cv[d0];
            s1[u] = s1[u] * SCALE + Cv[d1];
        }

        // --- online softmax update ---
        float t0 = fmaxf(fmaxf(s0[0], s0[1]), fmaxf(s0[2], s0[3]));
        float t1 = fmaxf(fmaxf(s1[0], s1[1]), fmaxf(s1[2], s1[3]));
        t0 = warp_max(t0);
        t1 = warp_max(t1);
        float mn0 = fmaxf(m0, t0);
        float mn1 = fmaxf(m1, t1);
        float a0 = __expf(m0 - mn0);
        float a1 = __expf(m1 - mn1);

        float ps0 = 0.f, ps1 = 0.f;
        #pragma unroll
        for (int u = 0; u < 4; u++) {
            float p0 = __expf(s0[u] - mn0);
            float p1 = __expf(s1[u] - mn1);
            Ps[r0 * KT + lane + 32 * u] = p0;
            Ps[r1 * KT + lane + 32 * u] = p1;
            ps0 += p0; ps1 += p1;
        }
        ps0 = warp_sum(ps0);
        ps1 = warp_sum(ps1);
        l0 = l0 * a0 + ps0;
        l1 = l1 * a1 + ps1;
        #pragma unroll
        for (int t = 0; t < 4; t++) { acc0[t] *= a0; acc1[t] *= a1; }
        m0 = mn0; m1 = mn1;
        __syncwarp();

        // --- PV: acc[t] over dims lane + 32t ---
        const float* p0p = &Ps[r0 * KT];
        const float* p1p = &Ps[r1 * KT];
        #pragma unroll 4
        for (int j = 0; j < KT; j++) {
            float p0 = p0p[j], p1 = p1p[j];
            const float* vrow = &Vs[j * DV + lane];
            #pragma unroll
            for (int t = 0; t < 4; t++) {
                float vv = vrow[32 * t];
                acc0[t] += p0 * vv;
                acc1[t] += p1 * vv;
            }
        }
        __syncthreads();
    }

    float inv0 = 1.f / l0;
    float inv1 = 1.f / l1;
    float* o0 = out + ((size_t)(b * N + iq0)) * DIM + h * DV + lane;
    float* o1 = out + ((size_t)(b * N + iq1)) * DIM + h * DV + lane;
    #pragma unroll
    for (int t = 0; t < 4; t++) {
        o0[32 * t] = acc0[t] * inv0;
        o1[32 * t] = acc1[t] * inv1;
    }
}

// ======================= launch =======================
extern "C" void kernel_launch(void* const* d_in, const int* in_sizes, int n_in,
                              void* d_out, int out_size)
{
    const float* x     = (const float*)d_in[0];
    // d_in[1] = mask (unused by the reference)
    const float* W_qk  = (const float*)d_in[2];
    const float* W_v   = (const float*)d_in[3];
    const float* W_out = (const float*)d_in[4];
    const float* b_out = (const float*)d_in[5];
    const float* conv  = (const float*)d_in[6];
    float* out = (float*)d_out;

    float *qk_p, *v_p, *ao_p;
    cudaGetSymbolAddress((void**)&qk_p, g_qk);
    cudaGetSymbolAddress((void**)&v_p,  g_v);
    cudaGetSymbolAddress((void**)&ao_p, g_ao);

    cudaFuncSetAttribute(attn_kernel, cudaFuncAttributeMaxDynamicSharedMemorySize,
                         ATTN_SMEM_BYTES);

    dim3 gemm_grid(DIM / GBN, BN_ROWS / GBM);  // (8, 64)

    // 1) qk = x @ W_qk   [8192,1024]
    sgemm_kernel<<<gemm_grid, 256>>>(x, W_qk, nullptr, qk_p, BN_ROWS, DIM, DIM);
    // 2) v = x @ W_v     [8192,1024]
    sgemm_kernel<<<gemm_grid, 256>>>(x, W_v, nullptr, v_p, BN_ROWS, DIM, DIM);
    // 3) attention -> g_ao [8192,1024]
    dim3 attn_grid(N / ROWS, HEADS, B);        // (128, 8, 4)
    attn_kernel<<<attn_grid, 256, ATTN_SMEM_BYTES>>>(qk_p, v_p, conv, ao_p);
    // 4) out = g_ao @ W_out + b_out
    sgemm_kernel<<<gemm_grid, 256>>>(ao_p, W_out, b_out, out, BN_ROWS, DIM, DIM);
}

// round 2
// speedup vs baseline: 1.3190x; 1.3190x over previous
#include <cuda_runtime.h>
#include <math_constants.h>
#include <stdint.h>

// Problem constants
#define B 4
#define N 2048
#define DIM 1024
#define HEADS 8
#define DQK 64
#define DV 128
#define MAX_POS 10
#define SCALE 0.125f   // 64^-0.5
#define BN_ROWS (B*N)  // 8192

// -------- scratch (device globals: allocation-free) --------
__device__ float g_qk[(size_t)BN_ROWS * DIM];  // q | k packed: [8192, 1024]
__device__ float g_v [(size_t)BN_ROWS * DIM];  // [8192, 1024]
__device__ float g_ao[(size_t)BN_ROWS * DIM];  // attention output [8192, 1024]

// ======================= TF32 tensor-core GEMM =======================
// C[M,N] = A[M,K] @ Bm[K,N] (+ bias[N]). Row-major. M,N,K multiples of 128/16.
// CTA tile 128x128x16, 8 warps (2x4), warp tile 64x32, mma.m16n8k8.tf32.

#define GBM 128
#define GBN 128
#define GBK 16
#define ASTRIDE 20    // GBK + 4  -> conflict-free A frag loads
#define BSTRIDE 136   // GBN + 8  -> conflict-free B frag loads

__device__ __forceinline__ uint32_t f2tf32(float x) {
    uint32_t r;
    asm("cvt.rna.tf32.f32 %0, %1;" : "=r"(r) : "f"(x));
    return r;
}

__device__ __forceinline__ void mma_tf32(float c[4], const uint32_t a[4], const uint32_t b[2]) {
    asm volatile(
        "mma.sync.aligned.m16n8k8.row.col.f32.tf32.tf32.f32 "
        "{%0,%1,%2,%3}, {%4,%5,%6,%7}, {%8,%9}, {%0,%1,%2,%3};"
        : "+f"(c[0]), "+f"(c[1]), "+f"(c[2]), "+f"(c[3])
        : "r"(a[0]), "r"(a[1]), "r"(a[2]), "r"(a[3]), "r"(b[0]), "r"(b[1]));
}

__global__ __launch_bounds__(256, 2)
void sgemm_tf32_kernel(const float* __restrict__ A, const float* __restrict__ Bm,
                       const float* __restrict__ bias, float* __restrict__ C,
                       int M, int Nn, int K)
{
    __shared__ uint32_t As[GBM * ASTRIDE];  // As[m][k], stride 20
    __shared__ uint32_t Bs[GBK * BSTRIDE];  // Bs[k][n], stride 136

    const int tid  = threadIdx.x;
    const int lane = tid & 31;
    const int w    = tid >> 5;          // 0..7
    const int wm   = w >> 2;            // 0..1
    const int wn   = w & 3;             // 0..3
    const int g    = lane >> 2;         // groupID 0..7
    const int r    = lane & 3;          // threadID in group 0..3

    const int bx = blockIdx.x, by = blockIdx.y;

    const float* Ablk = A  + (size_t)(by * GBM) * K;
    const float* Bblk = Bm + (size_t)(bx * GBN);

    // staging indices
    const int aRow = tid >> 2;          // 0..63 (two passes: +0, +64)
    const int aC4  = (tid & 3) << 2;    // 0,4,8,12
    const int bRow = tid >> 5;          // 0..7 (two passes: +0, +8)
    const int bC4  = (tid & 31) << 2;   // 0..124

    float acc[4][4][4];
    #pragma unroll
    for (int mt = 0; mt < 4; mt++)
        #pragma unroll
        for (int nt = 0; nt < 4; nt++)
            #pragma unroll
            for (int i = 0; i < 4; i++) acc[mt][nt][i] = 0.f;

    for (int k0 = 0; k0 < K; k0 += GBK) {
        // ---- stage A tile [128 x 16] into As[m][k] (stride 20), tf32-rounded ----
        #pragma unroll
        for (int p = 0; p < 2; p++) {
            int row = aRow + p * 64;
            float4 a4 = *(const float4*)(Ablk + (size_t)row * K + k0 + aC4);
            uint4 u;
            u.x = f2tf32(a4.x); u.y = f2tf32(a4.y);
            u.z = f2tf32(a4.z); u.w = f2tf32(a4.w);
            *(uint4*)&As[row * ASTRIDE + aC4] = u;   // 80B row stride: 16B-aligned
        }
        // ---- stage B tile [16 x 128] into Bs[k][n] (stride 136), tf32-rounded ----
        #pragma unroll
        for (int p = 0; p < 2; p++) {
            int row = bRow + p * 8;
            float4 b4 = *(const float4*)(Bblk + (size_t)(k0 + row) * Nn + bC4);
            uint4 u;
            u.x = f2tf32(b4.x); u.y = f2tf32(b4.y);
            u.z = f2tf32(b4.z); u.w = f2tf32(b4.w);
            *(uint4*)&Bs[row * BSTRIDE + bC4] = u;   // 544B row stride: 16B-aligned
        }
        __syncthreads();

        #pragma unroll
        for (int kk = 0; kk < GBK; kk += 8) {
            // load A fragments: 4 m-tiles
            uint32_t af[4][4];
            #pragma unroll
            for (int mt = 0; mt < 4; mt++) {
                int m0 = wm * 64 + mt * 16 + g;
                int c0 = kk + r;
                af[mt][0] = As[m0       * ASTRIDE + c0];
                af[mt][1] = As[(m0 + 8) * ASTRIDE + c0];
                af[mt][2] = As[m0       * ASTRIDE + c0 + 4];
                af[mt][3] = As[(m0 + 8) * ASTRIDE + c0 + 4];
            }
            // load B fragments: 4 n-tiles
            uint32_t bf[4][2];
            #pragma unroll
            for (int nt = 0; nt < 4; nt++) {
                int n0 = wn * 32 + nt * 8 + g;
                bf[nt][0] = Bs[(kk + r)     * BSTRIDE + n0];
                bf[nt][1] = Bs[(kk + r + 4) * BSTRIDE + n0];
            }
            // 16 MMAs
            #pragma unroll
            for (int mt = 0; mt < 4; mt++)
                #pragma unroll
                for (int nt = 0; nt < 4; nt++)
                    mma_tf32(acc[mt][nt], af[mt], bf[nt]);
        }
        __syncthreads();
    }

    // ---- epilogue ----
    #pragma unroll
    for (int mt = 0; mt < 4; mt++) {
        int row0 = by * GBM + wm * 64 + mt * 16 + g;
        #pragma unroll
        for (int nt = 0; nt < 4; nt++) {
            int col = bx * GBN + wn * 32 + nt * 8 + r * 2;
            float b0 = 0.f, b1 = 0.f;
            if (bias != nullptr) { b0 = bias[col]; b1 = bias[col + 1]; }
            float2 v0 = make_float2(acc[mt][nt][0] + b0, acc[mt][nt][1] + b1);
            float2 v1 = make_float2(acc[mt][nt][2] + b0, acc[mt][nt][3] + b1);
            *(float2*)(C + (size_t)row0 * Nn + col)       = v0;
            *(float2*)(C + (size_t)(row0 + 8) * Nn + col) = v1;
        }
    }
}

// ======================= Flash attention (unchanged, exact fp32) =======================
#define KT 128
#define ROWS 16
#define KPAD 65

#define SM_KS   0
#define SM_VS   (SM_KS + KT*KPAD)
#define SM_QS   (SM_VS + KT*DV)
#define SM_PS   (SM_QS + ROWS*DQK)
#define SM_CV   (SM_PS + ROWS*KT)
#define SM_FLOATS (SM_CV + 32)
#define ATTN_SMEM_BYTES (SM_FLOATS * 4)

__device__ __forceinline__ float warp_max(float v) {
    #pragma unroll
    for (int o = 16; o > 0; o >>= 1) v = fmaxf(v, __shfl_xor_sync(0xffffffffu, v, o));
    return v;
}
__device__ __forceinline__ float warp_sum(float v) {
    #pragma unroll
    for (int o = 16; o > 0; o >>= 1) v += __shfl_xor_sync(0xffffffffu, v, o);
    return v;
}

__global__ __launch_bounds__(256)
void attn_kernel(const float* __restrict__ qk, const float* __restrict__ vbuf,
                 const float* __restrict__ conv, float* __restrict__ out)
{
    extern __shared__ float sm[];
    float* Ks = sm + SM_KS;
    float* Vs = sm + SM_VS;
    float* Qs = sm + SM_QS;
    float* Ps = sm + SM_PS;
    float* Cv = sm + SM_CV;

    const int tid  = threadIdx.x;
    const int lane = tid & 31;
    const int w    = tid >> 5;
    const int h    = blockIdx.y;
    const int b    = blockIdx.z;
    const int i0   = blockIdx.x * ROWS;

    if (tid < 2 * MAX_POS + 1) Cv[tid] = conv[h * (2 * MAX_POS + 1) + tid];

    {
        int rr = tid >> 4;
        int d4 = (tid & 15) << 2;
        const float* qrow = qk + ((size_t)(b * N + i0 + rr)) * DIM + h * DQK;
        *(float4*)&Qs[rr * DQK + d4] = *(const float4*)(qrow + d4);
    }
    __syncthreads();

    const int r0 = w * 2, r1 = w * 2 + 1;
    const int iq0 = i0 + r0, iq1 = i0 + r1;

    float m0 = -CUDART_INF_F, m1 = -CUDART_INF_F;
    float l0 = 0.f, l1 = 0.f;
    float acc0[4] = {0.f, 0.f, 0.f, 0.f};
    float acc1[4] = {0.f, 0.f, 0.f, 0.f};

    for (int j0 = 0; j0 < N; j0 += KT) {
        #pragma unroll
        for (int t = tid; t < KT * 16; t += 256) {
            int row = t >> 4;
            int d4  = (t & 15) << 2;
            float4 kv = *(const float4*)(qk + ((size_t)(b * N + j0 + row)) * DIM
                                          + HEADS * DQK + h * DQK + d4);
            float* dst = &Ks[row * KPAD + d4];
            dst[0] = kv.x; dst[1] = kv.y; dst[2] = kv.z; dst[3] = kv.w;
        }
        #pragma unroll
        for (int t = tid; t < KT * 32; t += 256) {
            int row = t >> 5;
            int d4  = (t & 31) << 2;
            float4 vv = *(const float4*)(vbuf + ((size_t)(b * N + j0 + row)) * DIM
                                          + h * DV + d4);
            *(float4*)&Vs[row * DV + d4] = vv;
        }
        __syncthreads();

        float s0[4] = {0.f, 0.f, 0.f, 0.f};
        float s1[4] = {0.f, 0.f, 0.f, 0.f};
        const float* q0p = &Qs[r0 * DQK];
        const float* q1p = &Qs[r1 * DQK];
        #pragma unroll 4
        for (int d = 0; d < DQK; d++) {
            float q0 = q0p[d], q1 = q1p[d];
            #pragma unroll
            for (int u = 0; u < 4; u++) {
                float kv = Ks[(lane + 32 * u) * KPAD + d];
                s0[u] += q0 * kv;
                s1[u] += q1 * kv;
            }
        }
        #pragma unroll
        for (int u = 0; u < 4; u++) {
            int j = j0 + lane + 32 * u;
            int d0 = min(max(j - iq0, -MAX_POS), MAX_POS) + MAX_POS;
            int d1 = min(max(j - iq1, -MAX_POS), MAX_POS) + MAX_POS;
            s0[u] = s0[u] * SCALE + Cv[d0];
            s1[u] = s1[u] * SCALE + Cv[d1];
        }

        float t0 = fmaxf(fmaxf(s0[0], s0[1]), fmaxf(s0[2], s0[3]));
        float t1 = fmaxf(fmaxf(s1[0], s1[1]), fmaxf(s1[2], s1[3]));
        t0 = warp_max(t0);
        t1 = warp_max(t1);
        float mn0 = fmaxf(m0, t0);
        float mn1 = fmaxf(m1, t1);
        float a0 = __expf(m0 - mn0);
        float a1 = __expf(m1 - mn1);

        float ps0 = 0.f, ps1 = 0.f;
        #pragma unroll
        for (int u = 0; u < 4; u++) {
            float p0 = __expf(s0[u] - mn0);
            float p1 = __expf(s1[u] - mn1);
            Ps[r0 * KT + lane + 32 * u] = p0;
            Ps[r1 * KT + lane + 32 * u] = p1;
            ps0 += p0; ps1 += p1;
        }
        ps0 = warp_sum(ps0);
        ps1 = warp_sum(ps1);
        l0 = l0 * a0 + ps0;
        l1 = l1 * a1 + ps1;
        #pragma unroll
        for (int t = 0; t < 4; t++) { acc0[t] *= a0; acc1[t] *= a1; }
        m0 = mn0; m1 = mn1;
        __syncwarp();

        const float* p0p = &Ps[r0 * KT];
        const float* p1p = &Ps[r1 * KT];
        #pragma unroll 4
        for (int j = 0; j < KT; j++) {
            float p0 = p0p[j], p1 = p1p[j];
            const float* vrow = &Vs[j * DV + lane];
            #pragma unroll
            for (int t = 0; t < 4; t++) {
                float vv = vrow[32 * t];
                acc0[t] += p0 * vv;
                acc1[t] += p1 * vv;
            }
        }
        __syncthreads();
    }

    float inv0 = 1.f / l0;
    float inv1 = 1.f / l1;
    float* o0 = out + ((size_t)(b * N + iq0)) * DIM + h * DV + lane;
    float* o1 = out + ((size_t)(b * N + iq1)) * DIM + h * DV + lane;
    #pragma unroll
    for (int t = 0; t < 4; t++) {
        o0[32 * t] = acc0[t] * inv0;
        o1[32 * t] = acc1[t] * inv1;
    }
}

// ======================= launch =======================
extern "C" void kernel_launch(void* const* d_in, const int* in_sizes, int n_in,
                              void* d_out, int out_size)
{
    const float* x     = (const float*)d_in[0];
    // d_in[1] = mask (unused by the reference)
    const float* W_qk  = (const float*)d_in[2];
    const float* W_v   = (const float*)d_in[3];
    const float* W_out = (const float*)d_in[4];
    const float* b_out = (const float*)d_in[5];
    const float* conv  = (const float*)d_in[6];
    float* out = (float*)d_out;

    float *qk_p, *v_p, *ao_p;
    cudaGetSymbolAddress((void**)&qk_p, g_qk);
    cudaGetSymbolAddress((void**)&v_p,  g_v);
    cudaGetSymbolAddress((void**)&ao_p, g_ao);

    cudaFuncSetAttribute(attn_kernel, cudaFuncAttributeMaxDynamicSharedMemorySize,
                         ATTN_SMEM_BYTES);

    dim3 gemm_grid(DIM / GBN, BN_ROWS / GBM);  // (8, 64)

    // 1) qk = x @ W_qk   [8192,1024]
    sgemm_tf32_kernel<<<gemm_grid, 256>>>(x, W_qk, nullptr, qk_p, BN_ROWS, DIM, DIM);
    // 2) v = x @ W_v     [8192,1024]
    sgemm_tf32_kernel<<<gemm_grid, 256>>>(x, W_v, nullptr, v_p, BN_ROWS, DIM, DIM);
    // 3) attention -> g_ao [8192,1024]
    dim3 attn_grid(N / ROWS, HEADS, B);        // (128, 8, 4)
    attn_kernel<<<attn_grid, 256, ATTN_SMEM_BYTES>>>(qk_p, v_p, conv, ao_p);
    // 4) out = g_ao @ W_out + b_out
    sgemm_tf32_kernel<<<gemm_grid, 256>>>(ao_p, W_out, b_out, out, BN_ROWS, DIM, DIM);
}

// round 3
// speedup vs baseline: 2.4627x; 1.8671x over previous
#include <cuda_runtime.h>
#include <math_constants.h>
#include <stdint.h>

// Problem constants
#define B 4
#define N 2048
#define DIM 1024
#define HEADS 8
#define DQK 64
#define DV 128
#define MAX_POS 10
#define SCALE 0.125f   // 64^-0.5
#define BN_ROWS (B*N)  // 8192

// -------- scratch (device globals: allocation-free) --------
__device__ float g_qk[(size_t)BN_ROWS * DIM];  // q | k packed: [8192, 1024]
__device__ float g_v [(size_t)BN_ROWS * DIM];  // [8192, 1024]
__device__ float g_ao[(size_t)BN_ROWS * DIM];  // attention output [8192, 1024]

// ---------------- tf32 helpers ----------------
__device__ __forceinline__ uint32_t f2tf32(float x) {
    uint32_t r;
    asm("cvt.rna.tf32.f32 %0, %1;" : "=r"(r) : "f"(x));
    return r;
}

__device__ __forceinline__ void mma_tf32(float c[4], const uint32_t a[4], const uint32_t b[2]) {
    asm volatile(
        "mma.sync.aligned.m16n8k8.row.col.f32.tf32.tf32.f32 "
        "{%0,%1,%2,%3}, {%4,%5,%6,%7}, {%8,%9}, {%0,%1,%2,%3};"
        : "+f"(c[0]), "+f"(c[1]), "+f"(c[2]), "+f"(c[3])
        : "r"(a[0]), "r"(a[1]), "r"(a[2]), "r"(a[3]), "r"(b[0]), "r"(b[1]));
}

// ======================= 3xTF32 tensor-core GEMM (~fp32 accurate) =======================
// C[M,N] = A@Bm (+bias). CTA tile 128x128x16, 8 warps (2x4), warp tile 64x32.
#define GBM 128
#define GBN 128
#define GBK 16
#define ASTRIDE 20
#define BSTRIDE 136

__global__ __launch_bounds__(256, 2)
void gemm3x_kernel(const float* __restrict__ A, const float* __restrict__ Bm,
                   const float* __restrict__ bias, float* __restrict__ C,
                   int M, int Nn, int K)
{
    __shared__ uint32_t AsH[GBM * ASTRIDE];
    __shared__ uint32_t AsL[GBM * ASTRIDE];
    __shared__ uint32_t BsH[GBK * BSTRIDE];
    __shared__ uint32_t BsL[GBK * BSTRIDE];

    const int tid  = threadIdx.x;
    const int lane = tid & 31;
    const int w    = tid >> 5;
    const int wm   = w >> 2;
    const int wn   = w & 3;
    const int g    = lane >> 2;
    const int r    = lane & 3;

    const int bx = blockIdx.x, by = blockIdx.y;

    const float* Ablk = A  + (size_t)(by * GBM) * K;
    const float* Bblk = Bm + (size_t)(bx * GBN);

    const int aRow = tid >> 2;
    const int aC4  = (tid & 3) << 2;
    const int bRow = tid >> 5;
    const int bC4  = (tid & 31) << 2;

    float acc[4][4][4];
    #pragma unroll
    for (int mt = 0; mt < 4; mt++)
        #pragma unroll
        for (int nt = 0; nt < 4; nt++)
            #pragma unroll
            for (int i = 0; i < 4; i++) acc[mt][nt][i] = 0.f;

    for (int k0 = 0; k0 < K; k0 += GBK) {
        #pragma unroll
        for (int p = 0; p < 2; p++) {
            int row = aRow + p * 64;
            float4 a4 = *(const float4*)(Ablk + (size_t)row * K + k0 + aC4);
            uint4 uh, ul;
            uh.x = f2tf32(a4.x); ul.x = f2tf32(a4.x - __uint_as_float(uh.x));
            uh.y = f2tf32(a4.y); ul.y = f2tf32(a4.y - __uint_as_float(uh.y));
            uh.z = f2tf32(a4.z); ul.z = f2tf32(a4.z - __uint_as_float(uh.z));
            uh.w = f2tf32(a4.w); ul.w = f2tf32(a4.w - __uint_as_float(uh.w));
            *(uint4*)&AsH[row * ASTRIDE + aC4] = uh;
            *(uint4*)&AsL[row * ASTRIDE + aC4] = ul;
        }
        #pragma unroll
        for (int p = 0; p < 2; p++) {
            int row = bRow + p * 8;
            float4 b4 = *(const float4*)(Bblk + (size_t)(k0 + row) * Nn + bC4);
            uint4 uh, ul;
            uh.x = f2tf32(b4.x); ul.x = f2tf32(b4.x - __uint_as_float(uh.x));
            uh.y = f2tf32(b4.y); ul.y = f2tf32(b4.y - __uint_as_float(uh.y));
            uh.z = f2tf32(b4.z); ul.z = f2tf32(b4.z - __uint_as_float(uh.z));
            uh.w = f2tf32(b4.w); ul.w = f2tf32(b4.w - __uint_as_float(uh.w));
            *(uint4*)&BsH[row * BSTRIDE + bC4] = uh;
            *(uint4*)&BsL[row * BSTRIDE + bC4] = ul;
        }
        __syncthreads();

        #pragma unroll
        for (int kk = 0; kk < GBK; kk += 8) {
            uint32_t bH[4][2], bL[4][2];
            #pragma unroll
            for (int nt = 0; nt < 4; nt++) {
                int n0 = wn * 32 + nt * 8 + g;
                bH[nt][0] = BsH[(kk + r)     * BSTRIDE + n0];
                bH[nt][1] = BsH[(kk + r + 4) * BSTRIDE + n0];
                bL[nt][0] = BsL[(kk + r)     * BSTRIDE + n0];
                bL[nt][1] = BsL[(kk + r + 4) * BSTRIDE + n0];
            }
            #pragma unroll
            for (int mt = 0; mt < 4; mt++) {
                int m0 = wm * 64 + mt * 16 + g;
                uint32_t aH[4], aL[4];
                aH[0] = AsH[m0       * ASTRIDE + kk + r];
                aH[1] = AsH[(m0 + 8) * ASTRIDE + kk + r];
                aH[2] = AsH[m0       * ASTRIDE + kk + r + 4];
                aH[3] = AsH[(m0 + 8) * ASTRIDE + kk + r + 4];
                aL[0] = AsL[m0       * ASTRIDE + kk + r];
                aL[1] = AsL[(m0 + 8) * ASTRIDE + kk + r];
                aL[2] = AsL[m0       * ASTRIDE + kk + r + 4];
                aL[3] = AsL[(m0 + 8) * ASTRIDE + kk + r + 4];
                #pragma unroll
                for (int nt = 0; nt < 4; nt++) {
                    mma_tf32(acc[mt][nt], aL, bH[nt]);
                    mma_tf32(acc[mt][nt], aH, bL[nt]);
                    mma_tf32(acc[mt][nt], aH, bH[nt]);
                }
            }
        }
        __syncthreads();
    }

    #pragma unroll
    for (int mt = 0; mt < 4; mt++) {
        int row0 = by * GBM + wm * 64 + mt * 16 + g;
        #pragma unroll
        for (int nt = 0; nt < 4; nt++) {
            int col = bx * GBN + wn * 32 + nt * 8 + r * 2;
            float b0 = 0.f, b1 = 0.f;
            if (bias != nullptr) { b0 = bias[col]; b1 = bias[col + 1]; }
            float2 v0 = make_float2(acc[mt][nt][0] + b0, acc[mt][nt][1] + b1);
            float2 v1 = make_float2(acc[mt][nt][2] + b0, acc[mt][nt][3] + b1);
            *(float2*)(C + (size_t)row0 * Nn + col)       = v0;
            *(float2*)(C + (size_t)(row0 + 8) * Nn + col) = v1;
        }
    }
}

// ======================= Tensor-core flash attention =======================
// 128 threads (4 warps), 64 q-rows per CTA (16 per warp), 64-key tiles.
// S = Q K^T with K natural layout as col-major B. PV computed as (PV)^T = V^T P^T
// so V natural layout is the A operand; P acc->B frags via intra-quad shuffles.
#define AKT 64
#define QT  64
#define QS_STRIDE 68
#define KS_STRIDE 68
#define VS_STRIDE 136

#define A_QS 0
#define A_KS (A_QS + QT*QS_STRIDE)
#define A_VS (A_KS + AKT*KS_STRIDE)
#define A_CV (A_VS + AKT*VS_STRIDE)
#define A_TOT (A_CV + 32)
#define ATTN_SMEM_BYTES (A_TOT * 4)

__global__ __launch_bounds__(128, 3)
void attn_tc_kernel(const float* __restrict__ qk, const float* __restrict__ vbuf,
                    const float* __restrict__ conv, float* __restrict__ out)
{
    extern __shared__ uint32_t smu[];
    uint32_t* Qs = smu + A_QS;
    uint32_t* Ks = smu + A_KS;
    uint32_t* Vs = smu + A_VS;
    float*    Cv = (float*)(smu + A_CV);

    const int tid  = threadIdx.x;
    const int lane = tid & 31;
    const int w    = tid >> 5;
    const int g    = lane >> 2;
    const int r    = lane & 3;
    const int h    = blockIdx.y;
    const int b    = blockIdx.z;
    const int i0   = blockIdx.x * QT;
    const uint32_t full = 0xffffffffu;

    if (tid < 2 * MAX_POS + 1) Cv[tid] = conv[h * (2 * MAX_POS + 1) + tid];

    // stage Q (64 rows x 64 dims), tf32-rounded
    for (int t = tid; t < QT * 16; t += 128) {
        int row = t >> 4, c4 = (t & 15) << 2;
        float4 v = *(const float4*)(qk + ((size_t)(b * N + i0 + row)) * DIM + h * DQK + c4);
        uint4 u;
        u.x = f2tf32(v.x); u.y = f2tf32(v.y); u.z = f2tf32(v.z); u.w = f2tf32(v.w);
        *(uint4*)&Qs[row * QS_STRIDE + c4] = u;
    }

    float m_lo = -CUDART_INF_F, m_hi = -CUDART_INF_F;
    float l_lo = 0.f, l_hi = 0.f;
    float oacc[8][2][4];
    #pragma unroll
    for (int mt = 0; mt < 8; mt++)
        #pragma unroll
        for (int nt = 0; nt < 2; nt++)
            #pragma unroll
            for (int i = 0; i < 4; i++) oacc[mt][nt][i] = 0.f;

    const int ilo = i0 + w * 16 + g;
    const int ihi = ilo + 8;
    const int srcA = (lane & ~3) | (r >> 1);
    const int srcB = srcA + 2;
    const bool pr  = (r & 1);

    for (int j0 = 0; j0 < N; j0 += AKT) {
        // stage K tile (64x64) and V tile (64x128), tf32-rounded
        for (int t = tid; t < AKT * 16; t += 128) {
            int row = t >> 4, c4 = (t & 15) << 2;
            float4 v = *(const float4*)(qk + ((size_t)(b * N + j0 + row)) * DIM
                                         + HEADS * DQK + h * DQK + c4);
            uint4 u;
            u.x = f2tf32(v.x); u.y = f2tf32(v.y); u.z = f2tf32(v.z); u.w = f2tf32(v.w);
            *(uint4*)&Ks[row * KS_STRIDE + c4] = u;
        }
        for (int t = tid; t < AKT * 32; t += 128) {
            int row = t >> 5, c4 = (t & 31) << 2;
            float4 v = *(const float4*)(vbuf + ((size_t)(b * N + j0 + row)) * DIM + h * DV + c4);
            uint4 u;
            u.x = f2tf32(v.x); u.y = f2tf32(v.y); u.z = f2tf32(v.z); u.w = f2tf32(v.w);
            *(uint4*)&Vs[row * VS_STRIDE + c4] = u;
        }
        __syncthreads();

        // ---- S = Q K^T : per warp S[16, 64] ----
        float sacc[8][4];
        #pragma unroll
        for (int nt = 0; nt < 8; nt++)
            #pragma unroll
            for (int i = 0; i < 4; i++) sacc[nt][i] = 0.f;

        const int qrow = w * 16 + g;
        #pragma unroll
        for (int kt = 0; kt < 8; kt++) {
            uint32_t qa[4];
            qa[0] = Qs[ qrow      * QS_STRIDE + kt * 8 + r];
            qa[1] = Qs[(qrow + 8) * QS_STRIDE + kt * 8 + r];
            qa[2] = Qs[ qrow      * QS_STRIDE + kt * 8 + r + 4];
            qa[3] = Qs[(qrow + 8) * QS_STRIDE + kt * 8 + r + 4];
            #pragma unroll
            for (int nt = 0; nt < 8; nt++) {
                uint32_t bf[2];
                bf[0] = Ks[(nt * 8 + g) * KS_STRIDE + kt * 8 + r];
                bf[1] = Ks[(nt * 8 + g) * KS_STRIDE + kt * 8 + r + 4];
                mma_tf32(sacc[nt], qa, bf);
            }
        }

        // ---- scale + relative-position bias + row max ----
        float rx_lo = -CUDART_INF_F, rx_hi = -CUDART_INF_F;
        #pragma unroll
        for (int nt = 0; nt < 8; nt++) {
            int j = j0 + nt * 8 + 2 * r;
            int d00 = min(max(j     - ilo, -MAX_POS), MAX_POS) + MAX_POS;
            int d01 = min(max(j + 1 - ilo, -MAX_POS), MAX_POS) + MAX_POS;
            int d10 = min(max(j     - ihi, -MAX_POS), MAX_POS) + MAX_POS;
            int d11 = min(max(j + 1 - ihi, -MAX_POS), MAX_POS) + MAX_POS;
            sacc[nt][0] = sacc[nt][0] * SCALE + Cv[d00];
            sacc[nt][1] = sacc[nt][1] * SCALE + Cv[d01];
            sacc[nt][2] = sacc[nt][2] * SCALE + Cv[d10];
            sacc[nt][3] = sacc[nt][3] * SCALE + Cv[d11];
            rx_lo = fmaxf(rx_lo, fmaxf(sacc[nt][0], sacc[nt][1]));
            rx_hi = fmaxf(rx_hi, fmaxf(sacc[nt][2], sacc[nt][3]));
        }
        rx_lo = fmaxf(rx_lo, __shfl_xor_sync(full, rx_lo, 1));
        rx_lo = fmaxf(rx_lo, __shfl_xor_sync(full, rx_lo, 2));
        rx_hi = fmaxf(rx_hi, __shfl_xor_sync(full, rx_hi, 1));
        rx_hi = fmaxf(rx_hi, __shfl_xor_sync(full, rx_hi, 2));

        float mn_lo = fmaxf(m_lo, rx_lo);
        float mn_hi = fmaxf(m_hi, rx_hi);
        float al_lo = __expf(m_lo - mn_lo);
        float al_hi = __expf(m_hi - mn_hi);
        m_lo = mn_lo; m_hi = mn_hi;

        // ---- exp -> P (tf32), partial row sums ----
        uint32_t Pf[8][4];
        float ls_lo = 0.f, ls_hi = 0.f;
        #pragma unroll
        for (int nt = 0; nt < 8; nt++) {
            float p0 = __expf(sacc[nt][0] - m_lo);
            float p1 = __expf(sacc[nt][1] - m_lo);
            float p2 = __expf(sacc[nt][2] - m_hi);
            float p3 = __expf(sacc[nt][3] - m_hi);
            ls_lo += p0 + p1;
            ls_hi += p2 + p3;
            Pf[nt][0] = f2tf32(p0); Pf[nt][1] = f2tf32(p1);
            Pf[nt][2] = f2tf32(p2); Pf[nt][3] = f2tf32(p3);
        }
        l_lo = l_lo * al_lo + ls_lo;
        l_hi = l_hi * al_hi + ls_hi;

        // ---- rescale out accumulators (alpha per q-column) ----
        float aq0  = __shfl_sync(full, al_lo, 8 * r);
        float aq1  = __shfl_sync(full, al_lo, 8 * r + 4);
        float aq0h = __shfl_sync(full, al_hi, 8 * r);
        float aq1h = __shfl_sync(full, al_hi, 8 * r + 4);
        #pragma unroll
        for (int mt = 0; mt < 8; mt++) {
            oacc[mt][0][0] *= aq0;  oacc[mt][0][1] *= aq1;
            oacc[mt][0][2] *= aq0;  oacc[mt][0][3] *= aq1;
            oacc[mt][1][0] *= aq0h; oacc[mt][1][1] *= aq1h;
            oacc[mt][1][2] *= aq0h; oacc[mt][1][3] *= aq1h;
        }

        // ---- (PV)^T = V^T P^T ----
        #pragma unroll
        for (int kt = 0; kt < 8; kt++) {
            uint32_t s0 = __shfl_sync(full, Pf[kt][0], srcA);
            uint32_t s1 = __shfl_sync(full, Pf[kt][1], srcA);
            uint32_t t0 = __shfl_sync(full, Pf[kt][0], srcB);
            uint32_t t1 = __shfl_sync(full, Pf[kt][1], srcB);
            uint32_t bl[2];
            bl[0] = pr ? s1 : s0;
            bl[1] = pr ? t1 : t0;
            uint32_t s2 = __shfl_sync(full, Pf[kt][2], srcA);
            uint32_t s3 = __shfl_sync(full, Pf[kt][3], srcA);
            uint32_t t2 = __shfl_sync(full, Pf[kt][2], srcB);
            uint32_t t3 = __shfl_sync(full, Pf[kt][3], srcB);
            uint32_t bh[2];
            bh[0] = pr ? s3 : s2;
            bh[1] = pr ? t3 : t2;
            #pragma unroll
            for (int mt = 0; mt < 8; mt++) {
                uint32_t vf[4];
                vf[0] = Vs[(kt * 8 + r)     * VS_STRIDE + mt * 16 + g];
                vf[1] = Vs[(kt * 8 + r)     * VS_STRIDE + mt * 16 + 8 + g];
                vf[2] = Vs[(kt * 8 + r + 4) * VS_STRIDE + mt * 16 + g];
                vf[3] = Vs[(kt * 8 + r + 4) * VS_STRIDE + mt * 16 + 8 + g];
                mma_tf32(oacc[mt][0], vf, bl);
                mma_tf32(oacc[mt][1], vf, bh);
            }
        }
        __syncthreads();
    }

    // ---- epilogue: normalize and write ----
    l_lo += __shfl_xor_sync(full, l_lo, 1);
    l_lo += __shfl_xor_sync(full, l_lo, 2);
    l_hi += __shfl_xor_sync(full, l_hi, 1);
    l_hi += __shfl_xor_sync(full, l_hi, 2);
    float inv_lo = 1.f / l_lo;
    float inv_hi = 1.f / l_hi;
    float iq0  = __shfl_sync(full, inv_lo, 8 * r);
    float iq1  = __shfl_sync(full, inv_lo, 8 * r + 4);
    float iq0h = __shfl_sync(full, inv_hi, 8 * r);
    float iq1h = __shfl_sync(full, inv_hi, 8 * r + 4);

    const size_t rbase = (size_t)(b * N + i0 + w * 16);
    #pragma unroll
    for (int mt = 0; mt < 8; mt++) {
        int dcol = h * DV + mt * 16 + g;
        out[(rbase + 2 * r    ) * DIM + dcol    ] = oacc[mt][0][0] * iq0;
        out[(rbase + 2 * r + 1) * DIM + dcol    ] = oacc[mt][0][1] * iq1;
        out[(rbase + 2 * r    ) * DIM + dcol + 8] = oacc[mt][0][2] * iq0;
        out[(rbase + 2 * r + 1) * DIM + dcol + 8] = oacc[mt][0][3] * iq1;
        out[(rbase + 8 + 2 * r    ) * DIM + dcol    ] = oacc[mt][1][0] * iq0h;
        out[(rbase + 8 + 2 * r + 1) * DIM + dcol    ] = oacc[mt][1][1] * iq1h;
        out[(rbase + 8 + 2 * r    ) * DIM + dcol + 8] = oacc[mt][1][2] * iq0h;
        out[(rbase + 8 + 2 * r + 1) * DIM + dcol + 8] = oacc[mt][1][3] * iq1h;
    }
}

// ======================= launch =======================
extern "C" void kernel_launch(void* const* d_in, const int* in_sizes, int n_in,
                              void* d_out, int out_size)
{
    const float* x     = (const float*)d_in[0];
    // d_in[1] = mask (unused by the reference)
    const float* W_qk  = (const float*)d_in[2];
    const float* W_v   = (const float*)d_in[3];
    const float* W_out = (const float*)d_in[4];
    const float* b_out = (const float*)d_in[5];
    const float* conv  = (const float*)d_in[6];
    float* out = (float*)d_out;

    float *qk_p, *v_p, *ao_p;
    cudaGetSymbolAddress((void**)&qk_p, g_qk);
    cudaGetSymbolAddress((void**)&v_p,  g_v);
    cudaGetSymbolAddress((void**)&ao_p, g_ao);

    cudaFuncSetAttribute(attn_tc_kernel, cudaFuncAttributeMaxDynamicSharedMemorySize,
                         ATTN_SMEM_BYTES);

    dim3 gemm_grid(DIM / GBN, BN_ROWS / GBM);  // (8, 64)

    // 1) qk = x @ W_qk
    gemm3x_kernel<<<gemm_grid, 256>>>(x, W_qk, nullptr, qk_p, BN_ROWS, DIM, DIM);
    // 2) v = x @ W_v
    gemm3x_kernel<<<gemm_grid, 256>>>(x, W_v, nullptr, v_p, BN_ROWS, DIM, DIM);
    // 3) attention -> g_ao
    dim3 attn_grid(N / QT, HEADS, B);          // (32, 8, 4)
    attn_tc_kernel<<<attn_grid, 128, ATTN_SMEM_BYTES>>>(qk_p, v_p, conv, ao_p);
    // 4) out = g_ao @ W_out + b_out
    gemm3x_kernel<<<gemm_grid, 256>>>(ao_p, W_out, b_out, out, BN_ROWS, DIM, DIM);
}

// round 4
// speedup vs baseline: 3.1542x; 1.2808x over previous
#include <cuda_runtime.h>
#include <math_constants.h>
#include <stdint.h>

// Problem constants
#define B 4
#define N 2048
#define DIM 1024
#define HEADS 8
#define DQK 64
#define DV 128
#define MAX_POS 10
#define SCALE 0.125f   // 64^-0.5
#define BN_ROWS (B*N)  // 8192

// -------- scratch (device globals: allocation-free) --------
__device__ float g_qk[(size_t)BN_ROWS * DIM];  // q | k packed: [8192, 1024]
__device__ float g_v [(size_t)BN_ROWS * DIM];  // [8192, 1024]
__device__ float g_ao[(size_t)BN_ROWS * DIM];  // attention output [8192, 1024]

// ---------------- tf32 helpers ----------------
__device__ __forceinline__ uint32_t f2tf32(float x) {
    uint32_t r;
    asm("cvt.rna.tf32.f32 %0, %1;" : "=r"(r) : "f"(x));
    return r;
}

__device__ __forceinline__ void mma_tf32(float c[4], const uint32_t a[4], const uint32_t b[2]) {
    asm volatile(
        "mma.sync.aligned.m16n8k8.row.col.f32.tf32.tf32.f32 "
        "{%0,%1,%2,%3}, {%4,%5,%6,%7}, {%8,%9}, {%0,%1,%2,%3};"
        : "+f"(c[0]), "+f"(c[1]), "+f"(c[2]), "+f"(c[3])
        : "r"(a[0]), "r"(a[1]), "r"(a[2]), "r"(a[3]), "r"(b[0]), "r"(b[1]));
}

// ======================= 2xTF32 tensor-core GEMM, double-buffered =======================
// C = A @ Bm (+bias). Result = tf32(A) @ B exactly (B split hi/lo).
// CTA tile 128x128x16, 8 warps (2x4), warp tile 64x32.
// Double-buffered smem; global loads register-staged one k-tile ahead.
#define GBM 128
#define GBN 128
#define GBK 16
#define ASTRIDE 20
#define BSTRIDE 136
#define A_BUF (GBM*ASTRIDE)                   // 2560 words
#define B_BUF (GBK*BSTRIDE)                   // 2176 words
#define GEMM_SMEM_WORDS (2*A_BUF + 4*B_BUF)   // 13824 words
#define GEMM_SMEM_BYTES (GEMM_SMEM_WORDS*4)   // 55296 bytes

__global__ __launch_bounds__(256, 2)
void gemm2x_kernel(const float* __restrict__ A,
                   const float* __restrict__ B0, const float* __restrict__ B1,
                   const float* __restrict__ bias,
                   float* __restrict__ C0, float* __restrict__ C1,
                   int nx, int M, int Nn, int K)
{
    extern __shared__ uint32_t smg[];
    uint32_t* AsT = smg;                      // [2][A_BUF]  tf32(A)
    uint32_t* BsH = smg + 2 * A_BUF;          // [2][B_BUF]
    uint32_t* BsL = smg + 2 * A_BUF + 2 * B_BUF;

    const int tid  = threadIdx.x;
    const int lane = tid & 31;
    const int w    = tid >> 5;
    const int wm   = w >> 2;
    const int wn   = w & 3;
    const int g    = lane >> 2;
    const int r    = lane & 3;

    int bx = blockIdx.x;
    const int by = blockIdx.y;
    const float* Bm = B0;
    float* C = C0;
    if (bx >= nx) { Bm = B1; C = C1; bx -= nx; }

    const float* Ablk = A  + (size_t)(by * GBM) * K;
    const float* Bblk = Bm + (size_t)(bx * GBN);

    const int aRow = tid >> 2;           // 0..63 (+64 second pass)
    const int aC4  = (tid & 3) << 2;
    const int bRow = tid >> 5;           // 0..7 (+8 second pass)
    const int bC4  = (tid & 31) << 2;

    float acc[4][4][4];
    #pragma unroll
    for (int mt = 0; mt < 4; mt++)
        #pragma unroll
        for (int nt = 0; nt < 4; nt++)
            #pragma unroll
            for (int i = 0; i < 4; i++) acc[mt][nt][i] = 0.f;

    float4 aR0, aR1, bR0, bR1;   // register staging for next k-tile

    #define LDG_TILE(k0)                                                          \
        do {                                                                      \
            aR0 = *(const float4*)(Ablk + (size_t)aRow * K + (k0) + aC4);         \
            aR1 = *(const float4*)(Ablk + (size_t)(aRow + 64) * K + (k0) + aC4);  \
            bR0 = *(const float4*)(Bblk + (size_t)((k0) + bRow) * Nn + bC4);      \
            bR1 = *(const float4*)(Bblk + (size_t)((k0) + bRow + 8) * Nn + bC4);  \
        } while (0)

    #define STS_TILE(buf)                                                         \
        do {                                                                      \
            uint32_t* At = AsT + (buf) * A_BUF;                                   \
            uint32_t* Bh = BsH + (buf) * B_BUF;                                   \
            uint32_t* Bl = BsL + (buf) * B_BUF;                                   \
            uint4 u;                                                              \
            u.x = f2tf32(aR0.x); u.y = f2tf32(aR0.y);                             \
            u.z = f2tf32(aR0.z); u.w = f2tf32(aR0.w);                             \
            *(uint4*)&At[aRow * ASTRIDE + aC4] = u;                               \
            u.x = f2tf32(aR1.x); u.y = f2tf32(aR1.y);                             \
            u.z = f2tf32(aR1.z); u.w = f2tf32(aR1.w);                             \
            *(uint4*)&At[(aRow + 64) * ASTRIDE + aC4] = u;                        \
            uint4 uh, ul;                                                         \
            uh.x = f2tf32(bR0.x); ul.x = f2tf32(bR0.x - __uint_as_float(uh.x));   \
            uh.y = f2tf32(bR0.y); ul.y = f2tf32(bR0.y - __uint_as_float(uh.y));   \
            uh.z = f2tf32(bR0.z); ul.z = f2tf32(bR0.z - __uint_as_float(uh.z));   \
            uh.w = f2tf32(bR0.w); ul.w = f2tf32(bR0.w - __uint_as_float(uh.w));   \
            *(uint4*)&Bh[bRow * BSTRIDE + bC4] = uh;                              \
            *(uint4*)&Bl[bRow * BSTRIDE + bC4] = ul;                              \
            uh.x = f2tf32(bR1.x); ul.x = f2tf32(bR1.x - __uint_as_float(uh.x));   \
            uh.y = f2tf32(bR1.y); ul.y = f2tf32(bR1.y - __uint_as_float(uh.y));   \
            uh.z = f2tf32(bR1.z); ul.z = f2tf32(bR1.z - __uint_as_float(uh.z));   \
            uh.w = f2tf32(bR1.w); ul.w = f2tf32(bR1.w - __uint_as_float(uh.w));   \
            *(uint4*)&Bh[(bRow + 8) * BSTRIDE + bC4] = uh;                        \
            *(uint4*)&Bl[(bRow + 8) * BSTRIDE + bC4] = ul;                        \
        } while (0)

    const int NIT = K / GBK;

    LDG_TILE(0);
    STS_TILE(0);
    __syncthreads();

    for (int it = 0; it < NIT; it++) {
        const int cur = it & 1;
        if (it + 1 < NIT) LDG_TILE((it + 1) * GBK);

        const uint32_t* At = AsT + cur * A_BUF;
        const uint32_t* Bh = BsH + cur * B_BUF;
        const uint32_t* Bl = BsL + cur * B_BUF;

        #pragma unroll
        for (int kk = 0; kk < GBK; kk += 8) {
            uint32_t bh[4][2], bl[4][2];
            #pragma unroll
            for (int nt = 0; nt < 4; nt++) {
                int n0 = wn * 32 + nt * 8 + g;
                bh[nt][0] = Bh[(kk + r)     * BSTRIDE + n0];
                bh[nt][1] = Bh[(kk + r + 4) * BSTRIDE + n0];
                bl[nt][0] = Bl[(kk + r)     * BSTRIDE + n0];
                bl[nt][1] = Bl[(kk + r + 4) * BSTRIDE + n0];
            }
            #pragma unroll
            for (int mt = 0; mt < 4; mt++) {
                int m0 = wm * 64 + mt * 16 + g;
                uint32_t aH[4];
                aH[0] = At[m0       * ASTRIDE + kk + r];
                aH[1] = At[(m0 + 8) * ASTRIDE + kk + r];
                aH[2] = At[m0       * ASTRIDE + kk + r + 4];
                aH[3] = At[(m0 + 8) * ASTRIDE + kk + r + 4];
                #pragma unroll
                for (int nt = 0; nt < 4; nt++) {
                    mma_tf32(acc[mt][nt], aH, bl[nt]);
                    mma_tf32(acc[mt][nt], aH, bh[nt]);
                }
            }
        }

        if (it + 1 < NIT) STS_TILE(cur ^ 1);
        __syncthreads();
    }

    #pragma unroll
    for (int mt = 0; mt < 4; mt++) {
        int row0 = by * GBM + wm * 64 + mt * 16 + g;
        #pragma unroll
        for (int nt = 0; nt < 4; nt++) {
            int col = bx * GBN + wn * 32 + nt * 8 + r * 2;
            float b0 = 0.f, b1 = 0.f;
            if (bias != nullptr) { b0 = bias[col]; b1 = bias[col + 1]; }
            float2 v0 = make_float2(acc[mt][nt][0] + b0, acc[mt][nt][1] + b1);
            float2 v1 = make_float2(acc[mt][nt][2] + b0, acc[mt][nt][3] + b1);
            *(float2*)(C + (size_t)row0 * Nn + col)       = v0;
            *(float2*)(C + (size_t)(row0 + 8) * Nn + col) = v1;
        }
    }
}

// ======================= Tensor-core flash attention (unchanged) =======================
#define AKT 64
#define QT  64
#define QS_STRIDE 68
#define KS_STRIDE 68
#define VS_STRIDE 136

#define A_QS 0
#define A_KS (A_QS + QT*QS_STRIDE)
#define A_VS (A_KS + AKT*KS_STRIDE)
#define A_CV (A_VS + AKT*VS_STRIDE)
#define A_TOT (A_CV + 32)
#define ATTN_SMEM_BYTES (A_TOT * 4)

__global__ __launch_bounds__(128, 3)
void attn_tc_kernel(const float* __restrict__ qk, const float* __restrict__ vbuf,
                    const float* __restrict__ conv, float* __restrict__ out)
{
    extern __shared__ uint32_t smu[];
    uint32_t* Qs = smu + A_QS;
    uint32_t* Ks = smu + A_KS;
    uint32_t* Vs = smu + A_VS;
    float*    Cv = (float*)(smu + A_CV);

    const int tid  = threadIdx.x;
    const int lane = tid & 31;
    const int w    = tid >> 5;
    const int g    = lane >> 2;
    const int r    = lane & 3;
    const int h    = blockIdx.y;
    const int b    = blockIdx.z;
    const int i0   = blockIdx.x * QT;
    const uint32_t full = 0xffffffffu;

    if (tid < 2 * MAX_POS + 1) Cv[tid] = conv[h * (2 * MAX_POS + 1) + tid];

    for (int t = tid; t < QT * 16; t += 128) {
        int row = t >> 4, c4 = (t & 15) << 2;
        float4 v = *(const float4*)(qk + ((size_t)(b * N + i0 + row)) * DIM + h * DQK + c4);
        uint4 u;
        u.x = f2tf32(v.x); u.y = f2tf32(v.y); u.z = f2tf32(v.z); u.w = f2tf32(v.w);
        *(uint4*)&Qs[row * QS_STRIDE + c4] = u;
    }

    float m_lo = -CUDART_INF_F, m_hi = -CUDART_INF_F;
    float l_lo = 0.f, l_hi = 0.f;
    float oacc[8][2][4];
    #pragma unroll
    for (int mt = 0; mt < 8; mt++)
        #pragma unroll
        for (int nt = 0; nt < 2; nt++)
            #pragma unroll
            for (int i = 0; i < 4; i++) oacc[mt][nt][i] = 0.f;

    const int ilo = i0 + w * 16 + g;
    const int ihi = ilo + 8;
    const int srcA = (lane & ~3) | (r >> 1);
    const int srcB = srcA + 2;
    const bool pr  = (r & 1);

    for (int j0 = 0; j0 < N; j0 += AKT) {
        for (int t = tid; t < AKT * 16; t += 128) {
            int row = t >> 4, c4 = (t & 15) << 2;
            float4 v = *(const float4*)(qk + ((size_t)(b * N + j0 + row)) * DIM
                                         + HEADS * DQK + h * DQK + c4);
            uint4 u;
            u.x = f2tf32(v.x); u.y = f2tf32(v.y); u.z = f2tf32(v.z); u.w = f2tf32(v.w);
            *(uint4*)&Ks[row * KS_STRIDE + c4] = u;
        }
        for (int t = tid; t < AKT * 32; t += 128) {
            int row = t >> 5, c4 = (t & 31) << 2;
            float4 v = *(const float4*)(vbuf + ((size_t)(b * N + j0 + row)) * DIM + h * DV + c4);
            uint4 u;
            u.x = f2tf32(v.x); u.y = f2tf32(v.y); u.z = f2tf32(v.z); u.w = f2tf32(v.w);
            *(uint4*)&Vs[row * VS_STRIDE + c4] = u;
        }
        __syncthreads();

        float sacc[8][4];
        #pragma unroll
        for (int nt = 0; nt < 8; nt++)
            #pragma unroll
            for (int i = 0; i < 4; i++) sacc[nt][i] = 0.f;

        const int qrow = w * 16 + g;
        #pragma unroll
        for (int kt = 0; kt < 8; kt++) {
            uint32_t qa[4];
            qa[0] = Qs[ qrow      * QS_STRIDE + kt * 8 + r];
            qa[1] = Qs[(qrow + 8) * QS_STRIDE + kt * 8 + r];
            qa[2] = Qs[ qrow      * QS_STRIDE + kt * 8 + r + 4];
            qa[3] = Qs[(qrow + 8) * QS_STRIDE + kt * 8 + r + 4];
            #pragma unroll
            for (int nt = 0; nt < 8; nt++) {
                uint32_t bf[2];
                bf[0] = Ks[(nt * 8 + g) * KS_STRIDE + kt * 8 + r];
                bf[1] = Ks[(nt * 8 + g) * KS_STRIDE + kt * 8 + r + 4];
                mma_tf32(sacc[nt], qa, bf);
            }
        }

        float rx_lo = -CUDART_INF_F, rx_hi = -CUDART_INF_F;
        #pragma unroll
        for (int nt = 0; nt < 8; nt++) {
            int j = j0 + nt * 8 + 2 * r;
            int d00 = min(max(j     - ilo, -MAX_POS), MAX_POS) + MAX_POS;
            int d01 = min(max(j + 1 - ilo, -MAX_POS), MAX_POS) + MAX_POS;
            int d10 = min(max(j     - ihi, -MAX_POS), MAX_POS) + MAX_POS;
            int d11 = min(max(j + 1 - ihi, -MAX_POS), MAX_POS) + MAX_POS;
            sacc[nt][0] = sacc[nt][0] * SCALE + Cv[d00];
            sacc[nt][1] = sacc[nt][1] * SCALE + Cv[d01];
            sacc[nt][2] = sacc[nt][2] * SCALE + Cv[d10];
            sacc[nt][3] = sacc[nt][3] * SCALE + Cv[d11];
            rx_lo = fmaxf(rx_lo, fmaxf(sacc[nt][0], sacc[nt][1]));
            rx_hi = fmaxf(rx_hi, fmaxf(sacc[nt][2], sacc[nt][3]));
        }
        rx_lo = fmaxf(rx_lo, __shfl_xor_sync(full, rx_lo, 1));
        rx_lo = fmaxf(rx_lo, __shfl_xor_sync(full, rx_lo, 2));
        rx_hi = fmaxf(rx_hi, __shfl_xor_sync(full, rx_hi, 1));
        rx_hi = fmaxf(rx_hi, __shfl_xor_sync(full, rx_hi, 2));

        float mn_lo = fmaxf(m_lo, rx_lo);
        float mn_hi = fmaxf(m_hi, rx_hi);
        float al_lo = __expf(m_lo - mn_lo);
        float al_hi = __expf(m_hi - mn_hi);
        m_lo = mn_lo; m_hi = mn_hi;

        uint32_t Pf[8][4];
        float ls_lo = 0.f, ls_hi = 0.f;
        #pragma unroll
        for (int nt = 0; nt < 8; nt++) {
            float p0 = __expf(sacc[nt][0] - m_lo);
            float p1 = __expf(sacc[nt][1] - m_lo);
            float p2 = __expf(sacc[nt][2] - m_hi);
            float p3 = __expf(sacc[nt][3] - m_hi);
            ls_lo += p0 + p1;
            ls_hi += p2 + p3;
            Pf[nt][0] = f2tf32(p0); Pf[nt][1] = f2tf32(p1);
            Pf[nt][2] = f2tf32(p2); Pf[nt][3] = f2tf32(p3);
        }
        l_lo = l_lo * al_lo + ls_lo;
        l_hi = l_hi * al_hi + ls_hi;

        float aq0  = __shfl_sync(full, al_lo, 8 * r);
        float aq1  = __shfl_sync(full, al_lo, 8 * r + 4);
        float aq0h = __shfl_sync(full, al_hi, 8 * r);
        float aq1h = __shfl_sync(full, al_hi, 8 * r + 4);
        #pragma unroll
        for (int mt = 0; mt < 8; mt++) {
            oacc[mt][0][0] *= aq0;  oacc[mt][0][1] *= aq1;
            oacc[mt][0][2] *= aq0;  oacc[mt][0][3] *= aq1;
            oacc[mt][1][0] *= aq0h; oacc[mt][1][1] *= aq1h;
            oacc[mt][1][2] *= aq0h; oacc[mt][1][3] *= aq1h;
        }

        #pragma unroll
        for (int kt = 0; kt < 8; kt++) {
            uint32_t s0 = __shfl_sync(full, Pf[kt][0], srcA);
            uint32_t s1 = __shfl_sync(full, Pf[kt][1], srcA);
            uint32_t t0 = __shfl_sync(full, Pf[kt][0], srcB);
            uint32_t t1 = __shfl_sync(full, Pf[kt][1], srcB);
            uint32_t bl2[2];
            bl2[0] = pr ? s1 : s0;
            bl2[1] = pr ? t1 : t0;
            uint32_t s2 = __shfl_sync(full, Pf[kt][2], srcA);
            uint32_t s3 = __shfl_sync(full, Pf[kt][3], srcA);
            uint32_t t2 = __shfl_sync(full, Pf[kt][2], srcB);
            uint32_t t3 = __shfl_sync(full, Pf[kt][3], srcB);
            uint32_t bh2[2];
            bh2[0] = pr ? s3 : s2;
            bh2[1] = pr ? t3 : t2;
            #pragma unroll
            for (int mt = 0; mt < 8; mt++) {
                uint32_t vf[4];
                vf[0] = Vs[(kt * 8 + r)     * VS_STRIDE + mt * 16 + g];
                vf[1] = Vs[(kt * 8 + r)     * VS_STRIDE + mt * 16 + 8 + g];
                vf[2] = Vs[(kt * 8 + r + 4) * VS_STRIDE + mt * 16 + g];
                vf[3] = Vs[(kt * 8 + r + 4) * VS_STRIDE + mt * 16 + 8 + g];
                mma_tf32(oacc[mt][0], vf, bl2);
                mma_tf32(oacc[mt][1], vf, bh2);
            }
        }
        __syncthreads();
    }

    l_lo += __shfl_xor_sync(full, l_lo, 1);
    l_lo += __shfl_xor_sync(full, l_lo, 2);
    l_hi += __shfl_xor_sync(full, l_hi, 1);
    l_hi += __shfl_xor_sync(full, l_hi, 2);
    float inv_lo = 1.f / l_lo;
    float inv_hi = 1.f / l_hi;
    float iq0  = __shfl_sync(full, inv_lo, 8 * r);
    float iq1  = __shfl_sync(full, inv_lo, 8 * r + 4);
    float iq0h = __shfl_sync(full, inv_hi, 8 * r);
    float iq1h = __shfl_sync(full, inv_hi, 8 * r + 4);

    const size_t rbase = (size_t)(b * N + i0 + w * 16);
    #pragma unroll
    for (int mt = 0; mt < 8; mt++) {
        int dcol = h * DV + mt * 16 + g;
        out[(rbase + 2 * r    ) * DIM + dcol    ] = oacc[mt][0][0] * iq0;
        out[(rbase + 2 * r + 1) * DIM + dcol    ] = oacc[mt][0][1] * iq1;
        out[(rbase + 2 * r    ) * DIM + dcol + 8] = oacc[mt][0][2] * iq0;
        out[(rbase + 2 * r + 1) * DIM + dcol + 8] = oacc[mt][0][3] * iq1;
        out[(rbase + 8 + 2 * r    ) * DIM + dcol    ] = oacc[mt][1][0] * iq0h;
        out[(rbase + 8 + 2 * r + 1) * DIM + dcol    ] = oacc[mt][1][1] * iq1h;
        out[(rbase + 8 + 2 * r    ) * DIM + dcol + 8] = oacc[mt][1][2] * iq0h;
        out[(rbase + 8 + 2 * r + 1) * DIM + dcol + 8] = oacc[mt][1][3] * iq1h;
    }
}

// ======================= launch =======================
extern "C" void kernel_launch(void* const* d_in, const int* in_sizes, int n_in,
                              void* d_out, int out_size)
{
    const float* x     = (const float*)d_in[0];
    // d_in[1] = mask (unused by the reference)
    const float* W_qk  = (const float*)d_in[2];
    const float* W_v   = (const float*)d_in[3];
    const float* W_out = (const float*)d_in[4];
    const float* b_out = (const float*)d_in[5];
    const float* conv  = (const float*)d_in[6];
    float* out = (float*)d_out;

    float *qk_p, *v_p, *ao_p;
    cudaGetSymbolAddress((void**)&qk_p, g_qk);
    cudaGetSymbolAddress((void**)&v_p,  g_v);
    cudaGetSymbolAddress((void**)&ao_p, g_ao);

    cudaFuncSetAttribute(gemm2x_kernel, cudaFuncAttributeMaxDynamicSharedMemorySize,
                         GEMM_SMEM_BYTES);
    cudaFuncSetAttribute(attn_tc_kernel, cudaFuncAttributeMaxDynamicSharedMemorySize,
                         ATTN_SMEM_BYTES);

    // 1+2) fused: qk = x @ W_qk  and  v = x @ W_v  (shared A operand)
    dim3 qkv_grid(2 * DIM / GBN, BN_ROWS / GBM);   // (16, 64)
    gemm2x_kernel<<<qkv_grid, 256, GEMM_SMEM_BYTES>>>(
        x, W_qk, W_v, nullptr, qk_p, v_p, DIM / GBN, BN_ROWS, DIM, DIM);

    // 3) attention -> g_ao
    dim3 attn_grid(N / QT, HEADS, B);              // (32, 8, 4)
    attn_tc_kernel<<<attn_grid, 128, ATTN_SMEM_BYTES>>>(qk_p, v_p, conv, ao_p);

    // 4) out = g_ao @ W_out + b_out
    dim3 out_grid(DIM / GBN, BN_ROWS / GBM);       // (8, 64)
    gemm2x_kernel<<<out_grid, 256, GEMM_SMEM_BYTES>>>(
        ao_p, W_out, W_out, b_out, out, out, DIM / GBN, BN_ROWS, DIM, DIM);
}

// round 5
// speedup vs baseline: 3.1730x; 1.0060x over previous
#include <cuda_runtime.h>
#include <math_constants.h>
#include <stdint.h>

// Problem constants
#define B 4
#define N 2048
#define DIM 1024
#define HEADS 8
#define DQK 64
#define DV 128
#define MAX_POS 10
#define SCALE 0.125f   // 64^-0.5
#define BN_ROWS (B*N)  // 8192

// -------- scratch (device globals: allocation-free) --------
__device__ float g_qk[(size_t)BN_ROWS * DIM];  // q | k packed: [8192, 1024]
__device__ float g_v [(size_t)BN_ROWS * DIM];  // [8192, 1024]
__device__ float g_ao[(size_t)BN_ROWS * DIM];  // attention output [8192, 1024]

// ---------------- tf32 helpers ----------------
__device__ __forceinline__ uint32_t f2tf32(float x) {
    uint32_t r;
    asm("cvt.rna.tf32.f32 %0, %1;" : "=r"(r) : "f"(x));
    return r;
}

__device__ __forceinline__ void mma_tf32(float c[4], const uint32_t a[4], const uint32_t b[2]) {
    asm volatile(
        "mma.sync.aligned.m16n8k8.row.col.f32.tf32.tf32.f32 "
        "{%0,%1,%2,%3}, {%4,%5,%6,%7}, {%8,%9}, {%0,%1,%2,%3};"
        : "+f"(c[0]), "+f"(c[1]), "+f"(c[2]), "+f"(c[3])
        : "r"(a[0]), "r"(a[1]), "r"(a[2]), "r"(a[3]), "r"(b[0]), "r"(b[1]));
}

// ======================= 2xTF32 tensor-core GEMM, double-buffered =======================
// C = A @ Bm (+bias). Result = tf32(A) @ B exactly (B split hi/lo).
// CTA tile 128x128x16, 8 warps (2x4), warp tile 64x32.
// Double-buffered smem; global loads register-staged one k-tile ahead.
#define GBM 128
#define GBN 128
#define GBK 16
#define ASTRIDE 20
#define BSTRIDE 136
#define A_BUF (GBM*ASTRIDE)                   // 2560 words
#define B_BUF (GBK*BSTRIDE)                   // 2176 words
#define GEMM_SMEM_WORDS (2*A_BUF + 4*B_BUF)   // 13824 words
#define GEMM_SMEM_BYTES (GEMM_SMEM_WORDS*4)   // 55296 bytes

__global__ __launch_bounds__(256, 2)
void gemm2x_kernel(const float* __restrict__ A,
                   const float* __restrict__ B0, const float* __restrict__ B1,
                   const float* __restrict__ bias,
                   float* __restrict__ C0, float* __restrict__ C1,
                   int nx, int M, int Nn, int K)
{
    extern __shared__ uint32_t smg[];
    uint32_t* AsT = smg;                      // [2][A_BUF]  tf32(A)
    uint32_t* BsH = smg + 2 * A_BUF;          // [2][B_BUF]
    uint32_t* BsL = smg + 2 * A_BUF + 2 * B_BUF;

    const int tid  = threadIdx.x;
    const int lane = tid & 31;
    const int w    = tid >> 5;
    const int wm   = w >> 2;
    const int wn   = w & 3;
    const int g    = lane >> 2;
    const int r    = lane & 3;

    int bx = blockIdx.x;
    const int by = blockIdx.y;
    const float* Bm = B0;
    float* C = C0;
    if (bx >= nx) { Bm = B1; C = C1; bx -= nx; }

    const float* Ablk = A  + (size_t)(by * GBM) * K;
    const float* Bblk = Bm + (size_t)(bx * GBN);

    const int aRow = tid >> 2;           // 0..63 (+64 second pass)
    const int aC4  = (tid & 3) << 2;
    const int bRow = tid >> 5;           // 0..7 (+8 second pass)
    const int bC4  = (tid & 31) << 2;

    float acc[4][4][4];
    #pragma unroll
    for (int mt = 0; mt < 4; mt++)
        #pragma unroll
        for (int nt = 0; nt < 4; nt++)
            #pragma unroll
            for (int i = 0; i < 4; i++) acc[mt][nt][i] = 0.f;

    float4 aR0, aR1, bR0, bR1;   // register staging for next k-tile

    #define LDG_TILE(k0)                                                          \
        do {                                                                      \
            aR0 = *(const float4*)(Ablk + (size_t)aRow * K + (k0) + aC4);         \
            aR1 = *(const float4*)(Ablk + (size_t)(aRow + 64) * K + (k0) + aC4);  \
            bR0 = *(const float4*)(Bblk + (size_t)((k0) + bRow) * Nn + bC4);      \
            bR1 = *(const float4*)(Bblk + (size_t)((k0) + bRow + 8) * Nn + bC4);  \
        } while (0)

    #define STS_TILE(buf)                                                         \
        do {                                                                      \
            uint32_t* At = AsT + (buf) * A_BUF;                                   \
            uint32_t* Bh = BsH + (buf) * B_BUF;                                   \
            uint32_t* Bl = BsL + (buf) * B_BUF;                                   \
            uint4 u;                                                              \
            u.x = f2tf32(aR0.x); u.y = f2tf32(aR0.y);                             \
            u.z = f2tf32(aR0.z); u.w = f2tf32(aR0.w);                             \
            *(uint4*)&At[aRow * ASTRIDE + aC4] = u;                               \
            u.x = f2tf32(aR1.x); u.y = f2tf32(aR1.y);                             \
            u.z = f2tf32(aR1.z); u.w = f2tf32(aR1.w);                             \
            *(uint4*)&At[(aRow + 64) * ASTRIDE + aC4] = u;                        \
            uint4 uh, ul;                                                         \
            uh.x = f2tf32(bR0.x); ul.x = f2tf32(bR0.x - __uint_as_float(uh.x));   \
            uh.y = f2tf32(bR0.y); ul.y = f2tf32(bR0.y - __uint_as_float(uh.y));   \
            uh.z = f2tf32(bR0.z); ul.z = f2tf32(bR0.z - __uint_as_float(uh.z));   \
            uh.w = f2tf32(bR0.w); ul.w = f2tf32(bR0.w - __uint_as_float(uh.w));   \
            *(uint4*)&Bh[bRow * BSTRIDE + bC4] = uh;                              \
            *(uint4*)&Bl[bRow * BSTRIDE + bC4] = ul;                              \
            uh.x = f2tf32(bR1.x); ul.x = f2tf32(bR1.x - __uint_as_float(uh.x));   \
            uh.y = f2tf32(bR1.y); ul.y = f2tf32(bR1.y - __uint_as_float(uh.y));   \
            uh.z = f2tf32(bR1.z); ul.z = f2tf32(bR1.z - __uint_as_float(uh.z));   \
            uh.w = f2tf32(bR1.w); ul.w = f2tf32(bR1.w - __uint_as_float(uh.w));   \
            *(uint4*)&Bh[(bRow + 8) * BSTRIDE + bC4] = uh;                        \
            *(uint4*)&Bl[(bRow + 8) * BSTRIDE + bC4] = ul;                        \
        } while (0)

    const int NIT = K / GBK;

    LDG_TILE(0);
    STS_TILE(0);
    __syncthreads();

    for (int it = 0; it < NIT; it++) {
        const int cur = it & 1;
        if (it + 1 < NIT) LDG_TILE((it + 1) * GBK);

        const uint32_t* At = AsT + cur * A_BUF;
        const uint32_t* Bh = BsH + cur * B_BUF;
        const uint32_t* Bl = BsL + cur * B_BUF;

        #pragma unroll
        for (int kk = 0; kk < GBK; kk += 8) {
            uint32_t bh[4][2], bl[4][2];
            #pragma unroll
            for (int nt = 0; nt < 4; nt++) {
                int n0 = wn * 32 + nt * 8 + g;
                bh[nt][0] = Bh[(kk + r)     * BSTRIDE + n0];
                bh[nt][1] = Bh[(kk + r + 4) * BSTRIDE + n0];
                bl[nt][0] = Bl[(kk + r)     * BSTRIDE + n0];
                bl[nt][1] = Bl[(kk + r + 4) * BSTRIDE + n0];
            }
            #pragma unroll
            for (int mt = 0; mt < 4; mt++) {
                int m0 = wm * 64 + mt * 16 + g;
                uint32_t aH[4];
                aH[0] = At[m0       * ASTRIDE + kk + r];
                aH[1] = At[(m0 + 8) * ASTRIDE + kk + r];
                aH[2] = At[m0       * ASTRIDE + kk + r + 4];
                aH[3] = At[(m0 + 8) * ASTRIDE + kk + r + 4];
                #pragma unroll
                for (int nt = 0; nt < 4; nt++) {
                    mma_tf32(acc[mt][nt], aH, bl[nt]);
                    mma_tf32(acc[mt][nt], aH, bh[nt]);
                }
            }
        }

        if (it + 1 < NIT) STS_TILE(cur ^ 1);
        __syncthreads();
    }

    #pragma unroll
    for (int mt = 0; mt < 4; mt++) {
        int row0 = by * GBM + wm * 64 + mt * 16 + g;
        #pragma unroll
        for (int nt = 0; nt < 4; nt++) {
            int col = bx * GBN + wn * 32 + nt * 8 + r * 2;
            float b0 = 0.f, b1 = 0.f;
            if (bias != nullptr) { b0 = bias[col]; b1 = bias[col + 1]; }
            float2 v0 = make_float2(acc[mt][nt][0] + b0, acc[mt][nt][1] + b1);
            float2 v1 = make_float2(acc[mt][nt][2] + b0, acc[mt][nt][3] + b1);
            *(float2*)(C + (size_t)row0 * Nn + col)       = v0;
            *(float2*)(C + (size_t)(row0 + 8) * Nn + col) = v1;
        }
    }
}

// ======================= Tensor-core flash attention (unchanged) =======================
#define AKT 64
#define QT  64
#define QS_STRIDE 68
#define KS_STRIDE 68
#define VS_STRIDE 136

#define A_QS 0
#define A_KS (A_QS + QT*QS_STRIDE)
#define A_VS (A_KS + AKT*KS_STRIDE)
#define A_CV (A_VS + AKT*VS_STRIDE)
#define A_TOT (A_CV + 32)
#define ATTN_SMEM_BYTES (A_TOT * 4)

__global__ __launch_bounds__(128, 3)
void attn_tc_kernel(const float* __restrict__ qk, const float* __restrict__ vbuf,
                    const float* __restrict__ conv, float* __restrict__ out)
{
    extern __shared__ uint32_t smu[];
    uint32_t* Qs = smu + A_QS;
    uint32_t* Ks = smu + A_KS;
    uint32_t* Vs = smu + A_VS;
    float*    Cv = (float*)(smu + A_CV);

    const int tid  = threadIdx.x;
    const int lane = tid & 31;
    const int w    = tid >> 5;
    const int g    = lane >> 2;
    const int r    = lane & 3;
    const int h    = blockIdx.y;
    const int b    = blockIdx.z;
    const int i0   = blockIdx.x * QT;
    const uint32_t full = 0xffffffffu;

    if (tid < 2 * MAX_POS + 1) Cv[tid] = conv[h * (2 * MAX_POS + 1) + tid];

    for (int t = tid; t < QT * 16; t += 128) {
        int row = t >> 4, c4 = (t & 15) << 2;
        float4 v = *(const float4*)(qk + ((size_t)(b * N + i0 + row)) * DIM + h * DQK + c4);
        uint4 u;
        u.x = f2tf32(v.x); u.y = f2tf32(v.y); u.z = f2tf32(v.z); u.w = f2tf32(v.w);
        *(uint4*)&Qs[row * QS_STRIDE + c4] = u;
    }

    float m_lo = -CUDART_INF_F, m_hi = -CUDART_INF_F;
    float l_lo = 0.f, l_hi = 0.f;
    float oacc[8][2][4];
    #pragma unroll
    for (int mt = 0; mt < 8; mt++)
        #pragma unroll
        for (int nt = 0; nt < 2; nt++)
            #pragma unroll
            for (int i = 0; i < 4; i++) oacc[mt][nt][i] = 0.f;

    const int ilo = i0 + w * 16 + g;
    const int ihi = ilo + 8;
    const int srcA = (lane & ~3) | (r >> 1);
    const int srcB = srcA + 2;
    const bool pr  = (r & 1);

    for (int j0 = 0; j0 < N; j0 += AKT) {
        for (int t = tid; t < AKT * 16; t += 128) {
            int row = t >> 4, c4 = (t & 15) << 2;
            float4 v = *(const float4*)(qk + ((size_t)(b * N + j0 + row)) * DIM
                                         + HEADS * DQK + h * DQK + c4);
            uint4 u;
            u.x = f2tf32(v.x); u.y = f2tf32(v.y); u.z = f2tf32(v.z); u.w = f2tf32(v.w);
            *(uint4*)&Ks[row * KS_STRIDE + c4] = u;
        }
        for (int t = tid; t < AKT * 32; t += 128) {
            int row = t >> 5, c4 = (t & 31) << 2;
            float4 v = *(const float4*)(vbuf + ((size_t)(b * N + j0 + row)) * DIM + h * DV + c4);
            uint4 u;
            u.x = f2tf32(v.x); u.y = f2tf32(v.y); u.z = f2tf32(v.z); u.w = f2tf32(v.w);
            *(uint4*)&Vs[row * VS_STRIDE + c4] = u;
        }
        __syncthreads();

        float sacc[8][4];
        #pragma unroll
        for (int nt = 0; nt < 8; nt++)
            #pragma unroll
            for (int i = 0; i < 4; i++) sacc[nt][i] = 0.f;

        const int qrow = w * 16 + g;
        #pragma unroll
        for (int kt = 0; kt < 8; kt++) {
            uint32_t qa[4];
            qa[0] = Qs[ qrow      * QS_STRIDE + kt * 8 + r];
            qa[1] = Qs[(qrow + 8) * QS_STRIDE + kt * 8 + r];
            qa[2] = Qs[ qrow      * QS_STRIDE + kt * 8 + r + 4];
            qa[3] = Qs[(qrow + 8) * QS_STRIDE + kt * 8 + r + 4];
            #pragma unroll
            for (int nt = 0; nt < 8; nt++) {
                uint32_t bf[2];
                bf[0] = Ks[(nt * 8 + g) * KS_STRIDE + kt * 8 + r];
                bf[1] = Ks[(nt * 8 + g) * KS_STRIDE + kt * 8 + r + 4];
                mma_tf32(sacc[nt], qa, bf);
            }
        }

        float rx_lo = -CUDART_INF_F, rx_hi = -CUDART_INF_F;
        #pragma unroll
        for (int nt = 0; nt < 8; nt++) {
            int j = j0 + nt * 8 + 2 * r;
            int d00 = min(max(j     - ilo, -MAX_POS), MAX_POS) + MAX_POS;
            int d01 = min(max(j + 1 - ilo, -MAX_POS), MAX_POS) + MAX_POS;
            int d10 = min(max(j     - ihi, -MAX_POS), MAX_POS) + MAX_POS;
            int d11 = min(max(j + 1 - ihi, -MAX_POS), MAX_POS) + MAX_POS;
            sacc[nt][0] = sacc[nt][0] * SCALE + Cv[d00];
            sacc[nt][1] = sacc[nt][1] * SCALE + Cv[d01];
            sacc[nt][2] = sacc[nt][2] * SCALE + Cv[d10];
            sacc[nt][3] = sacc[nt][3] * SCALE + Cv[d11];
            rx_lo = fmaxf(rx_lo, fmaxf(sacc[nt][0], sacc[nt][1]));
            rx_hi = fmaxf(rx_hi, fmaxf(sacc[nt][2], sacc[nt][3]));
        }
        rx_lo = fmaxf(rx_lo, __shfl_xor_sync(full, rx_lo, 1));
        rx_lo = fmaxf(rx_lo, __shfl_xor_sync(full, rx_lo, 2));
        rx_hi = fmaxf(rx_hi, __shfl_xor_sync(full, rx_hi, 1));
        rx_hi = fmaxf(rx_hi, __shfl_xor_sync(full, rx_hi, 2));

        float mn_lo = fmaxf(m_lo, rx_lo);
        float mn_hi = fmaxf(m_hi, rx_hi);
        float al_lo = __expf(m_lo - mn_lo);
        float al_hi = __expf(m_hi - mn_hi);
        m_lo = mn_lo; m_hi = mn_hi;

        uint32_t Pf[8][4];
        float ls_lo = 0.f, ls_hi = 0.f;
        #pragma unroll
        for (int nt = 0; nt < 8; nt++) {
            float p0 = __expf(sacc[nt][0] - m_lo);
            float p1 = __expf(sacc[nt][1] - m_lo);
            float p2 = __expf(sacc[nt][2] - m_hi);
            float p3 = __expf(sacc[nt][3] - m_hi);
            ls_lo += p0 + p1;
            ls_hi += p2 + p3;
            Pf[nt][0] = f2tf32(p0); Pf[nt][1] = f2tf32(p1);
            Pf[nt][2] = f2tf32(p2); Pf[nt][3] = f2tf32(p3);
        }
        l_lo = l_lo * al_lo + ls_lo;
        l_hi = l_hi * al_hi + ls_hi;

        float aq0  = __shfl_sync(full, al_lo, 8 * r);
        float aq1  = __shfl_sync(full, al_lo, 8 * r + 4);
        float aq0h = __shfl_sync(full, al_hi, 8 * r);
        float aq1h = __shfl_sync(full, al_hi, 8 * r + 4);
        #pragma unroll
        for (int mt = 0; mt < 8; mt++) {
            oacc[mt][0][0] *= aq0;  oacc[mt][0][1] *= aq1;
            oacc[mt][0][2] *= aq0;  oacc[mt][0][3] *= aq1;
            oacc[mt][1][0] *= aq0h; oacc[mt][1][1] *= aq1h;
            oacc[mt][1][2] *= aq0h; oacc[mt][1][3] *= aq1h;
        }

        #pragma unroll
        for (int kt = 0; kt < 8; kt++) {
            uint32_t s0 = __shfl_sync(full, Pf[kt][0], srcA);
            uint32_t s1 = __shfl_sync(full, Pf[kt][1], srcA);
            uint32_t t0 = __shfl_sync(full, Pf[kt][0], srcB);
            uint32_t t1 = __shfl_sync(full, Pf[kt][1], srcB);
            uint32_t bl2[2];
            bl2[0] = pr ? s1 : s0;
            bl2[1] = pr ? t1 : t0;
            uint32_t s2 = __shfl_sync(full, Pf[kt][2], srcA);
            uint32_t s3 = __shfl_sync(full, Pf[kt][3], srcA);
            uint32_t t2 = __shfl_sync(full, Pf[kt][2], srcB);
            uint32_t t3 = __shfl_sync(full, Pf[kt][3], srcB);
            uint32_t bh2[2];
            bh2[0] = pr ? s3 : s2;
            bh2[1] = pr ? t3 : t2;
            #pragma unroll
            for (int mt = 0; mt < 8; mt++) {
                uint32_t vf[4];
                vf[0] = Vs[(kt * 8 + r)     * VS_STRIDE + mt * 16 + g];
                vf[1] = Vs[(kt * 8 + r)     * VS_STRIDE + mt * 16 + 8 + g];
                vf[2] = Vs[(kt * 8 + r + 4) * VS_STRIDE + mt * 16 + g];
                vf[3] = Vs[(kt * 8 + r + 4) * VS_STRIDE + mt * 16 + 8 + g];
                mma_tf32(oacc[mt][0], vf, bl2);
                mma_tf32(oacc[mt][1], vf, bh2);
            }
        }
        __syncthreads();
    }

    l_lo += __shfl_xor_sync(full, l_lo, 1);
    l_lo += __shfl_xor_sync(full, l_lo, 2);
    l_hi += __shfl_xor_sync(full, l_hi, 1);
    l_hi += __shfl_xor_sync(full, l_hi, 2);
    float inv_lo = 1.f / l_lo;
    float inv_hi = 1.f / l_hi;
    float iq0  = __shfl_sync(full, inv_lo, 8 * r);
    float iq1  = __shfl_sync(full, inv_lo, 8 * r + 4);
    float iq0h = __shfl_sync(full, inv_hi, 8 * r);
    float iq1h = __shfl_sync(full, inv_hi, 8 * r + 4);

    const size_t rbase = (size_t)(b * N + i0 + w * 16);
    #pragma unroll
    for (int mt = 0; mt < 8; mt++) {
        int dcol = h * DV + mt * 16 + g;
        out[(rbase + 2 * r    ) * DIM + dcol    ] = oacc[mt][0][0] * iq0;
        out[(rbase + 2 * r + 1) * DIM + dcol    ] = oacc[mt][0][1] * iq1;
        out[(rbase + 2 * r    ) * DIM + dcol + 8] = oacc[mt][0][2] * iq0;
        out[(rbase + 2 * r + 1) * DIM + dcol + 8] = oacc[mt][0][3] * iq1;
        out[(rbase + 8 + 2 * r    ) * DIM + dcol    ] = oacc[mt][1][0] * iq0h;
        out[(rbase + 8 + 2 * r + 1) * DIM + dcol    ] = oacc[mt][1][1] * iq1h;
        out[(rbase + 8 + 2 * r    ) * DIM + dcol + 8] = oacc[mt][1][2] * iq0h;
        out[(rbase + 8 + 2 * r + 1) * DIM + dcol + 8] = oacc[mt][1][3] * iq1h;
    }
}

// ======================= launch =======================
extern "C" void kernel_launch(void* const* d_in, const int* in_sizes, int n_in,
                              void* d_out, int out_size)
{
    const float* x     = (const float*)d_in[0];
    // d_in[1] = mask (unused by the reference)
    const float* W_qk  = (const float*)d_in[2];
    const float* W_v   = (const float*)d_in[3];
    const float* W_out = (const float*)d_in[4];
    const float* b_out = (const float*)d_in[5];
    const float* conv  = (const float*)d_in[6];
    float* out = (float*)d_out;

    float *qk_p, *v_p, *ao_p;
    cudaGetSymbolAddress((void**)&qk_p, g_qk);
    cudaGetSymbolAddress((void**)&v_p,  g_v);
    cudaGetSymbolAddress((void**)&ao_p, g_ao);

    cudaFuncSetAttribute(gemm2x_kernel, cudaFuncAttributeMaxDynamicSharedMemorySize,
                         GEMM_SMEM_BYTES);
    cudaFuncSetAttribute(attn_tc_kernel, cudaFuncAttributeMaxDynamicSharedMemorySize,
                         ATTN_SMEM_BYTES);

    // 1+2) fused: qk = x @ W_qk  and  v = x @ W_v  (shared A operand)
    dim3 qkv_grid(2 * DIM / GBN, BN_ROWS / GBM);   // (16, 64)
    gemm2x_kernel<<<qkv_grid, 256, GEMM_SMEM_BYTES>>>(
        x, W_qk, W_v, nullptr, qk_p, v_p, DIM / GBN, BN_ROWS, DIM, DIM);

    // 3) attention -> g_ao
    dim3 attn_grid(N / QT, HEADS, B);              // (32, 8, 4)
    attn_tc_kernel<<<attn_grid, 128, ATTN_SMEM_BYTES>>>(qk_p, v_p, conv, ao_p);

    // 4) out = g_ao @ W_out + b_out
    dim3 out_grid(DIM / GBN, BN_ROWS / GBM);       // (8, 64)
    gemm2x_kernel<<<out_grid, 256, GEMM_SMEM_BYTES>>>(
        ao_p, W_out, W_out, b_out, out, out, DIM / GBN, BN_ROWS, DIM, DIM);
}